// round 8
// baseline (speedup 1.0000x reference)
#include <cuda_runtime.h>

// SwinWindowAttention fused kernel: one CTA per window, fp32 with packed
// f32x2 FMA (sm_103a FFMA2) on all dense math.
// Phases: load x (+ stage bias/rel_idx) -> QKV gemm (3 passes, W transposed in
// smem) -> per-(head,row) attention with bias + softmax -> out-proj gemm.
// R2 fix: QK dot covers all 32 head dims (was 16 -> rel_err 0.615).
// R6: attention probabilities kept in registers (thread-private, audited safe).
// R7 fix: REVERT the R4 register-prefetch of weight tiles. Its load_w/store_w
//         only staged 16/128 columns (2 iters instead of 16) -> s_ws was 7/8
//         garbage -> rel_err 0.994. Back to the R2-proven fused stage_w.
// R8: resubmission of R7 verbatim (acquisition timeout; kernel never measured).

#define TOK 49
#define CD  128

namespace {
constexpr int THREADS = 256;
constexpr int HSTR    = 1576;              // padded per-head stride (floats); 1568+8 kills bank conflicts
constexpr int TSTR    = 4 * HSTR;          // per-tensor (q/k/v) stride = 6304
// smem layout (floats):
constexpr int OFF_X    = 0;                // x window [49][128], reused as attn output o   (6272)
constexpr int OFF_QKV  = 6272;             // q,k,v each [4][HSTR]                          (18912)
constexpr int OFF_WS   = 25184;            // staged weight tile transposed [128][132]      (16896)
constexpr int OFF_BIAS = 42080;            // bias_table staged [169*4]                     (676)
constexpr int OFF_RIDX = 42756;            // rel_idx staged [49*49] (as int)               (2401)
constexpr int SMEM_FLOATS = 45157;
constexpr int SMEM_BYTES  = SMEM_FLOATS * 4;   // 180628 B
constexpr float SCALE = 0.17677669529663687f;  // 32^-0.5
}

// ---- packed f32x2 helpers (sm_103a) ----------------------------------------
__device__ __forceinline__ unsigned long long pk2(float a, float b) {
    unsigned long long r;
    asm("mov.b64 %0, {%1, %2};" : "=l"(r)
        : "r"(__float_as_uint(a)), "r"(__float_as_uint(b)));
    return r;
}
__device__ __forceinline__ void fma2(unsigned long long& d,
                                     unsigned long long a, unsigned long long b) {
    asm("fma.rn.f32x2 %0, %1, %2, %3;" : "=l"(d) : "l"(a), "l"(b), "l"(d));
}
__device__ __forceinline__ void add2(unsigned long long& d, unsigned long long a) {
    asm("add.rn.f32x2 %0, %1, %2;" : "=l"(d) : "l"(a), "l"(d));
}
__device__ __forceinline__ float2 upk(unsigned long long v) {
    unsigned int lo, hi;
    asm("mov.b64 {%0, %1}, %2;" : "=r"(lo), "=r"(hi) : "l"(v));
    return make_float2(__uint_as_float(lo), __uint_as_float(hi));
}

// Stage a [128][128] row-major weight matrix into smem transposed:
// ws[k*132 + c] = w[c*128 + k].  16 iterations: 256 threads x 16 x float4
// = 16384 floats = the FULL tile.
__device__ __forceinline__ void stage_w(const float* __restrict__ wsrc, float* __restrict__ ws) {
    const int tid = threadIdx.x;
    #pragma unroll
    for (int it = 0; it < (128 * 32) / THREADS; ++it) {
        int idx = tid + it * THREADS;
        int c = idx >> 5;          // 0..127
        int l = idx & 31;          // k-group 0..31
        float4 v = *reinterpret_cast<const float4*>(wsrc + c * 128 + l * 4);
        int k = l * 4;
        ws[(k + 0) * 132 + c] = v.x;
        ws[(k + 1) * 132 + c] = v.y;
        ws[(k + 2) * 132 + c] = v.z;
        ws[(k + 3) * 132 + c] = v.w;
    }
}

// 7 rows x 4 cols register-tile GEMM over K=128 using f32x2 (col pairs).
__device__ __forceinline__ void gemm_7x4_f32x2(const float* __restrict__ xs,
                                               const float* __restrict__ ws,
                                               int r0, int c0,
                                               unsigned long long acc[7][2]) {
    #pragma unroll 4
    for (int k = 0; k < 128; k += 4) {
        unsigned long long wlo[4], whi[4];
        #pragma unroll
        for (int u = 0; u < 4; ++u) {
            ulonglong2 wv = *reinterpret_cast<const ulonglong2*>(ws + (k + u) * 132 + c0);
            wlo[u] = wv.x; whi[u] = wv.y;       // (c0,c0+1),(c0+2,c0+3)
        }
        #pragma unroll
        for (int r = 0; r < 7; ++r) {
            float4 xv = *reinterpret_cast<const float4*>(xs + (r0 + r) * CD + k);
            unsigned long long xx;
            xx = pk2(xv.x, xv.x); fma2(acc[r][0], xx, wlo[0]); fma2(acc[r][1], xx, whi[0]);
            xx = pk2(xv.y, xv.y); fma2(acc[r][0], xx, wlo[1]); fma2(acc[r][1], xx, whi[1]);
            xx = pk2(xv.z, xv.z); fma2(acc[r][0], xx, wlo[2]); fma2(acc[r][1], xx, whi[2]);
            xx = pk2(xv.w, xv.w); fma2(acc[r][0], xx, wlo[3]); fma2(acc[r][1], xx, whi[3]);
        }
    }
}

__global__ void __launch_bounds__(THREADS, 1)
swin_fused(const float* __restrict__ x,
           const float* __restrict__ qkv_w,
           const float* __restrict__ qkv_b,
           const float* __restrict__ out_w,
           const float* __restrict__ out_b,
           const float* __restrict__ bias_table,
           const int*   __restrict__ rel_idx,
           float* __restrict__ out)
{
    extern __shared__ float sm[];
    float* s_x    = sm + OFF_X;
    float* s_qkv  = sm + OFF_QKV;
    float* s_ws   = sm + OFF_WS;
    float* s_bias = sm + OFF_BIAS;
    int*   s_ridx = reinterpret_cast<int*>(sm + OFF_RIDX);

    const int tid = threadIdx.x;
    const float* xw = x + (size_t)blockIdx.x * (TOK * CD);

    // ---------------- Phase A: stage x window, bias table, rel_idx ------------------
    for (int i = tid; i < TOK * CD / 4; i += THREADS)
        reinterpret_cast<float4*>(s_x)[i] = reinterpret_cast<const float4*>(xw)[i];
    for (int i = tid; i < 676; i += THREADS)
        s_bias[i] = bias_table[i];
    for (int i = tid; i < 2401; i += THREADS)
        s_ridx[i] = rel_idx[i];

    const int rg = tid >> 5;            // 0..7 (7 active)
    const int cg = tid & 31;            // 0..31
    const int r0 = rg * 7;              // 49 = 7*7 rows
    const bool act224 = (tid < 224);

    // ---------------- Phase B: QKV = x @ qkv_w^T + qkv_b  (3 passes of 128 cols) ----
    for (int p = 0; p < 3; ++p) {
        __syncthreads();                          // x ready / prior-pass readers done
        stage_w(qkv_w + p * 16384, s_ws);
        __syncthreads();
        if (act224) {
            const int c0 = cg * 4;
            unsigned long long acc[7][2];
            float4 bv = *reinterpret_cast<const float4*>(qkv_b + p * 128 + c0);
            #pragma unroll
            for (int r = 0; r < 7; ++r) {
                acc[r][0] = pk2(bv.x, bv.y);
                acc[r][1] = pk2(bv.z, bv.w);
            }
            gemm_7x4_f32x2(s_x, s_ws, r0, c0, acc);
            // scatter into per-head layout: s_qkv[p*TSTR + h*HSTR + row*32 + d]
            const int h  = cg >> 3;
            const int d0 = (cg & 7) * 4;
            float* dst = s_qkv + p * TSTR + h * HSTR + d0;
            #pragma unroll
            for (int r = 0; r < 7; ++r) {
                float2 a = upk(acc[r][0]), b = upk(acc[r][1]);
                float4 v; v.x = a.x; v.y = a.y; v.z = b.x; v.w = b.y;
                *reinterpret_cast<float4*>(dst + (r0 + r) * 32) = v;
            }
        }
    }
    __syncthreads();

    // ---------------- Phase C: attention, one (head,row) per thread -----------------
    if (tid < 196) {
        const int h = tid / 49;
        const int i = tid - h * 49;
        // q row as packed f32x2 pairs: 8 x ulonglong2 = 32 floats (FULL head dim)
        const ulonglong2* qrow = reinterpret_cast<const ulonglong2*>(s_qkv + h * HSTR + i * 32);
        ulonglong2 qa[8];
        #pragma unroll
        for (int u = 0; u < 8; ++u) qa[u] = qrow[u];

        const float* kbase = s_qkv + TSTR     + h * HSTR;
        const float* vbase = s_qkv + 2 * TSTR + h * HSTR;
        const int*   ri    = s_ridx + i * 49;

        float pr[49];                       // per-thread probabilities: registers only
        float m = -1e30f;
        #pragma unroll
        for (int j = 0; j < 49; ++j) {
            const ulonglong2* kr = reinterpret_cast<const ulonglong2*>(kbase + j * 32);
            unsigned long long s0 = 0ull, s1 = 0ull, s2 = 0ull, s3 = 0ull;
            #pragma unroll
            for (int u = 0; u < 4; ++u) {        // 8 ulonglong2 = 32 dims
                ulonglong2 k0 = kr[2 * u], k1 = kr[2 * u + 1];
                fma2(s0, qa[2 * u].x,     k0.x);
                fma2(s1, qa[2 * u].y,     k0.y);
                fma2(s2, qa[2 * u + 1].x, k1.x);
                fma2(s3, qa[2 * u + 1].y, k1.y);
            }
            add2(s0, s1); add2(s2, s3); add2(s0, s2);
            float2 sp = upk(s0);
            float s = sp.x + sp.y;
            s = fmaf(s, SCALE, s_bias[ri[j] * 4 + h]);
            pr[j] = s;
            m = fmaxf(m, s);
        }
        float sum = 0.f;
        #pragma unroll
        for (int j = 0; j < 49; ++j) {
            float e = __expf(pr[j] - m);
            pr[j] = e;
            sum += e;
        }
        const float inv = 1.f / sum;

        unsigned long long o2[16];
        #pragma unroll
        for (int u = 0; u < 16; ++u) o2[u] = 0ull;
        #pragma unroll
        for (int j = 0; j < 49; ++j) {
            const unsigned long long pp = pk2(pr[j], pr[j]);
            const ulonglong2* vr = reinterpret_cast<const ulonglong2*>(vbase + j * 32);
            #pragma unroll
            for (int u = 0; u < 8; ++u) {
                ulonglong2 vv = vr[u];
                fma2(o2[2 * u + 0], pp, vv.x);
                fma2(o2[2 * u + 1], pp, vv.y);
            }
        }
        // write concat-head layout into s_x (x no longer needed): o_row[i][h*32+d]
        float* od = s_x + i * CD + h * 32;
        #pragma unroll
        for (int u = 0; u < 16; ++u) {
            float2 v = upk(o2[u]);
            od[2 * u + 0] = v.x * inv;
            od[2 * u + 1] = v.y * inv;
        }
    }
    __syncthreads();

    // ---------------- Phase D: out = o @ out_w^T + out_b -----------------------------
    stage_w(out_w, s_ws);                 // phase C done; s_ws free to overwrite
    __syncthreads();
    if (act224) {
        const int c0 = cg * 4;
        unsigned long long acc[7][2];
        float4 bv = *reinterpret_cast<const float4*>(out_b + c0);
        #pragma unroll
        for (int r = 0; r < 7; ++r) {
            acc[r][0] = pk2(bv.x, bv.y);
            acc[r][1] = pk2(bv.z, bv.w);
        }
        gemm_7x4_f32x2(s_x, s_ws, r0, c0, acc);
        float* dst = out + (size_t)blockIdx.x * (TOK * CD);
        #pragma unroll
        for (int r = 0; r < 7; ++r) {
            float2 a = upk(acc[r][0]), b = upk(acc[r][1]);
            float4 v; v.x = a.x; v.y = a.y; v.z = b.x; v.w = b.y;
            *reinterpret_cast<float4*>(dst + (r0 + r) * CD + c0) = v;
        }
    }
}

extern "C" void kernel_launch(void* const* d_in, const int* in_sizes, int n_in,
                              void* d_out, int out_size) {
    const float* x          = (const float*)d_in[0];
    const float* qkv_w      = (const float*)d_in[1];
    const float* qkv_b      = (const float*)d_in[2];
    const float* out_w      = (const float*)d_in[3];
    const float* out_b      = (const float*)d_in[4];
    const float* bias_table = (const float*)d_in[5];
    const int*   rel_idx    = (const int*)d_in[6];
    float* out = (float*)d_out;

    const int nwin = in_sizes[0] / (TOK * CD);   // 8192

    // idempotent, capture-safe (no stream work, no allocation)
    cudaFuncSetAttribute(swin_fused, cudaFuncAttributeMaxDynamicSharedMemorySize, SMEM_BYTES);
    swin_fused<<<nwin, THREADS, SMEM_BYTES>>>(x, qkv_w, qkv_b, out_w, out_b,
                                              bias_table, rel_idx, out);
}

// round 9
// speedup vs baseline: 1.4481x; 1.4481x over previous
#include <cuda_runtime.h>

// SwinWindowAttention fused kernel: one CTA per window, fp32 with packed
// f32x2 FMA (sm_103a FFMA2) on all dense math.
// R8 (PASS, 2993.8us): ncu showed L1TEX=75.8% binding, fma=29.7%.
// R9: (a) stage_w rewritten conflict-free: old version's STS was 4-way
//     bank-conflicted (stride-132 scalar stores) costing ~8k wavefronts/CTA;
//     new mapping = per-(k,4col) slot: 4 coalesced LDG.32 + 1 conflict-free
//     STS.128. Bit-identical smem image.
//     (b) out_w staged by warp 7 concurrently with Phase C attention
//     (tids 224-255 were idle there); removes the serial Phase-D stage.

#define TOK 49
#define CD  128

namespace {
constexpr int THREADS = 256;
constexpr int HSTR    = 1576;              // padded per-head stride (floats)
constexpr int TSTR    = 4 * HSTR;          // per-tensor (q/k/v) stride = 6304
// smem layout (floats):
constexpr int OFF_X    = 0;                // x window [49][128], reused as attn output o   (6272)
constexpr int OFF_QKV  = 6272;             // q,k,v each [4][HSTR]                          (18912)
constexpr int OFF_WS   = 25184;            // staged weight tile transposed [128][132]      (16896)
constexpr int OFF_BIAS = 42080;            // bias_table staged [169*4]                     (676)
constexpr int OFF_RIDX = 42756;            // rel_idx staged [49*49] (as int)               (2401)
constexpr int SMEM_FLOATS = 45157;
constexpr int SMEM_BYTES  = SMEM_FLOATS * 4;   // 180628 B
constexpr float SCALE = 0.17677669529663687f;  // 32^-0.5
}

// ---- packed f32x2 helpers (sm_103a) ----------------------------------------
__device__ __forceinline__ unsigned long long pk2(float a, float b) {
    unsigned long long r;
    asm("mov.b64 %0, {%1, %2};" : "=l"(r)
        : "r"(__float_as_uint(a)), "r"(__float_as_uint(b)));
    return r;
}
__device__ __forceinline__ void fma2(unsigned long long& d,
                                     unsigned long long a, unsigned long long b) {
    asm("fma.rn.f32x2 %0, %1, %2, %3;" : "=l"(d) : "l"(a), "l"(b), "l"(d));
}
__device__ __forceinline__ void add2(unsigned long long& d, unsigned long long a) {
    asm("add.rn.f32x2 %0, %1, %2;" : "=l"(d) : "l"(a), "l"(d));
}
__device__ __forceinline__ float2 upk(unsigned long long v) {
    unsigned int lo, hi;
    asm("mov.b64 {%0, %1}, %2;" : "=r"(lo), "=r"(hi) : "l"(v));
    return make_float2(__uint_as_float(lo), __uint_as_float(hi));
}

// Stage a [128][128] row-major weight matrix into smem transposed:
// ws[k*132 + c] = w[c*128 + k].
// Thread slot = (k, 4-col group): 4 coalesced scalar LDGs (lanes span
// consecutive k -> 128B lines) + one STS.128 at lane stride 528B
// (16*l mod 128 distinct within each 8-lane phase -> conflict-free).
__device__ __forceinline__ void stage_w(const float* __restrict__ wsrc, float* __restrict__ ws) {
    const int tid = threadIdx.x;
    #pragma unroll
    for (int it = 0; it < 16; ++it) {
        int idx = tid + it * THREADS;   // 0..4095
        int k  = idx & 127;             // row in transposed tile (lanes consecutive)
        int c0 = (idx >> 7) * 4;        // col group 0,4,...,124 (constant per warp)
        float a0 = wsrc[(c0 + 0) * 128 + k];
        float a1 = wsrc[(c0 + 1) * 128 + k];
        float a2 = wsrc[(c0 + 2) * 128 + k];
        float a3 = wsrc[(c0 + 3) * 128 + k];
        float4 v; v.x = a0; v.y = a1; v.z = a2; v.w = a3;
        *reinterpret_cast<float4*>(ws + k * 132 + c0) = v;
    }
}

// Same staging, executed by one warp (32 threads, t0 = lane 0..31).
__device__ __forceinline__ void stage_w_warp(const float* __restrict__ wsrc,
                                             float* __restrict__ ws, int t0) {
    #pragma unroll 4
    for (int it = 0; it < 128; ++it) {
        int idx = t0 + it * 32;         // 0..4095, lanes consecutive k
        int k  = idx & 127;
        int c0 = (idx >> 7) * 4;
        float a0 = wsrc[(c0 + 0) * 128 + k];
        float a1 = wsrc[(c0 + 1) * 128 + k];
        float a2 = wsrc[(c0 + 2) * 128 + k];
        float a3 = wsrc[(c0 + 3) * 128 + k];
        float4 v; v.x = a0; v.y = a1; v.z = a2; v.w = a3;
        *reinterpret_cast<float4*>(ws + k * 132 + c0) = v;
    }
}

// 7 rows x 4 cols register-tile GEMM over K=128 using f32x2 (col pairs).
__device__ __forceinline__ void gemm_7x4_f32x2(const float* __restrict__ xs,
                                               const float* __restrict__ ws,
                                               int r0, int c0,
                                               unsigned long long acc[7][2]) {
    #pragma unroll 4
    for (int k = 0; k < 128; k += 4) {
        unsigned long long wlo[4], whi[4];
        #pragma unroll
        for (int u = 0; u < 4; ++u) {
            ulonglong2 wv = *reinterpret_cast<const ulonglong2*>(ws + (k + u) * 132 + c0);
            wlo[u] = wv.x; whi[u] = wv.y;       // (c0,c0+1),(c0+2,c0+3)
        }
        #pragma unroll
        for (int r = 0; r < 7; ++r) {
            float4 xv = *reinterpret_cast<const float4*>(xs + (r0 + r) * CD + k);
            unsigned long long xx;
            xx = pk2(xv.x, xv.x); fma2(acc[r][0], xx, wlo[0]); fma2(acc[r][1], xx, whi[0]);
            xx = pk2(xv.y, xv.y); fma2(acc[r][0], xx, wlo[1]); fma2(acc[r][1], xx, whi[1]);
            xx = pk2(xv.z, xv.z); fma2(acc[r][0], xx, wlo[2]); fma2(acc[r][1], xx, whi[2]);
            xx = pk2(xv.w, xv.w); fma2(acc[r][0], xx, wlo[3]); fma2(acc[r][1], xx, whi[3]);
        }
    }
}

__global__ void __launch_bounds__(THREADS, 1)
swin_fused(const float* __restrict__ x,
           const float* __restrict__ qkv_w,
           const float* __restrict__ qkv_b,
           const float* __restrict__ out_w,
           const float* __restrict__ out_b,
           const float* __restrict__ bias_table,
           const int*   __restrict__ rel_idx,
           float* __restrict__ out)
{
    extern __shared__ float sm[];
    float* s_x    = sm + OFF_X;
    float* s_qkv  = sm + OFF_QKV;
    float* s_ws   = sm + OFF_WS;
    float* s_bias = sm + OFF_BIAS;
    int*   s_ridx = reinterpret_cast<int*>(sm + OFF_RIDX);

    const int tid = threadIdx.x;
    const float* xw = x + (size_t)blockIdx.x * (TOK * CD);

    // ---------------- Phase A: stage x window, bias table, rel_idx ------------------
    for (int i = tid; i < TOK * CD / 4; i += THREADS)
        reinterpret_cast<float4*>(s_x)[i] = reinterpret_cast<const float4*>(xw)[i];
    for (int i = tid; i < 676; i += THREADS)
        s_bias[i] = bias_table[i];
    for (int i = tid; i < 2401; i += THREADS)
        s_ridx[i] = rel_idx[i];

    const int rg = tid >> 5;            // 0..7 (7 active)
    const int cg = tid & 31;            // 0..31
    const int r0 = rg * 7;              // 49 = 7*7 rows
    const bool act224 = (tid < 224);

    // ---------------- Phase B: QKV = x @ qkv_w^T + qkv_b  (3 passes of 128 cols) ----
    for (int p = 0; p < 3; ++p) {
        __syncthreads();                          // x ready / prior-pass readers done
        stage_w(qkv_w + p * 16384, s_ws);
        __syncthreads();
        if (act224) {
            const int c0 = cg * 4;
            unsigned long long acc[7][2];
            float4 bv = *reinterpret_cast<const float4*>(qkv_b + p * 128 + c0);
            #pragma unroll
            for (int r = 0; r < 7; ++r) {
                acc[r][0] = pk2(bv.x, bv.y);
                acc[r][1] = pk2(bv.z, bv.w);
            }
            gemm_7x4_f32x2(s_x, s_ws, r0, c0, acc);
            // scatter into per-head layout: s_qkv[p*TSTR + h*HSTR + row*32 + d]
            const int h  = cg >> 3;
            const int d0 = (cg & 7) * 4;
            float* dst = s_qkv + p * TSTR + h * HSTR + d0;
            #pragma unroll
            for (int r = 0; r < 7; ++r) {
                float2 a = upk(acc[r][0]), b = upk(acc[r][1]);
                float4 v; v.x = a.x; v.y = a.y; v.z = b.x; v.w = b.y;
                *reinterpret_cast<float4*>(dst + (r0 + r) * 32) = v;
            }
        }
    }
    __syncthreads();

    // ---------------- Phase C: attention (tids<196) || stage out_w (warp 7) ---------
    if (tid < 196) {
        const int h = tid / 49;
        const int i = tid - h * 49;
        // q row as packed f32x2 pairs: 8 x ulonglong2 = 32 floats (FULL head dim)
        const ulonglong2* qrow = reinterpret_cast<const ulonglong2*>(s_qkv + h * HSTR + i * 32);
        ulonglong2 qa[8];
        #pragma unroll
        for (int u = 0; u < 8; ++u) qa[u] = qrow[u];

        const float* kbase = s_qkv + TSTR     + h * HSTR;
        const float* vbase = s_qkv + 2 * TSTR + h * HSTR;
        const int*   ri    = s_ridx + i * 49;

        float pr[49];                       // per-thread probabilities: registers only
        float m = -1e30f;
        #pragma unroll
        for (int j = 0; j < 49; ++j) {
            const ulonglong2* kr = reinterpret_cast<const ulonglong2*>(kbase + j * 32);
            unsigned long long s0 = 0ull, s1 = 0ull, s2 = 0ull, s3 = 0ull;
            #pragma unroll
            for (int u = 0; u < 4; ++u) {        // 8 ulonglong2 = 32 dims
                ulonglong2 k0 = kr[2 * u], k1 = kr[2 * u + 1];
                fma2(s0, qa[2 * u].x,     k0.x);
                fma2(s1, qa[2 * u].y,     k0.y);
                fma2(s2, qa[2 * u + 1].x, k1.x);
                fma2(s3, qa[2 * u + 1].y, k1.y);
            }
            add2(s0, s1); add2(s2, s3); add2(s0, s2);
            float2 sp = upk(s0);
            float s = sp.x + sp.y;
            s = fmaf(s, SCALE, s_bias[ri[j] * 4 + h]);
            pr[j] = s;
            m = fmaxf(m, s);
        }
        float sum = 0.f;
        #pragma unroll
        for (int j = 0; j < 49; ++j) {
            float e = __expf(pr[j] - m);
            pr[j] = e;
            sum += e;
        }
        const float inv = 1.f / sum;

        unsigned long long o2[16];
        #pragma unroll
        for (int u = 0; u < 16; ++u) o2[u] = 0ull;
        #pragma unroll
        for (int j = 0; j < 49; ++j) {
            const unsigned long long pp = pk2(pr[j], pr[j]);
            const ulonglong2* vr = reinterpret_cast<const ulonglong2*>(vbase + j * 32);
            #pragma unroll
            for (int u = 0; u < 8; ++u) {
                ulonglong2 vv = vr[u];
                fma2(o2[2 * u + 0], pp, vv.x);
                fma2(o2[2 * u + 1], pp, vv.y);
            }
        }
        // write concat-head layout into s_x (x no longer needed): o_row[i][h*32+d]
        float* od = s_x + i * CD + h * 32;
        #pragma unroll
        for (int u = 0; u < 16; ++u) {
            float2 v = upk(o2[u]);
            od[2 * u + 0] = v.x * inv;
            od[2 * u + 1] = v.y * inv;
        }
    } else if (tid >= 224) {
        // Warp 7 (idle in attention) stages out_w into s_ws concurrently.
        // s_ws not read since the post-Phase-B barrier -> safe to overwrite.
        stage_w_warp(out_w, s_ws, tid - 224);
    }
    __syncthreads();

    // ---------------- Phase D: out = o @ out_w^T + out_b -----------------------------
    if (act224) {
        const int c0 = cg * 4;
        unsigned long long acc[7][2];
        float4 bv = *reinterpret_cast<const float4*>(out_b + c0);
        #pragma unroll
        for (int r = 0; r < 7; ++r) {
            acc[r][0] = pk2(bv.x, bv.y);
            acc[r][1] = pk2(bv.z, bv.w);
        }
        gemm_7x4_f32x2(s_x, s_ws, r0, c0, acc);
        float* dst = out + (size_t)blockIdx.x * (TOK * CD);
        #pragma unroll
        for (int r = 0; r < 7; ++r) {
            float2 a = upk(acc[r][0]), b = upk(acc[r][1]);
            float4 v; v.x = a.x; v.y = a.y; v.z = b.x; v.w = b.y;
            *reinterpret_cast<float4*>(dst + (r0 + r) * CD + c0) = v;
        }
    }
}

extern "C" void kernel_launch(void* const* d_in, const int* in_sizes, int n_in,
                              void* d_out, int out_size) {
    const float* x          = (const float*)d_in[0];
    const float* qkv_w      = (const float*)d_in[1];
    const float* qkv_b      = (const float*)d_in[2];
    const float* out_w      = (const float*)d_in[3];
    const float* out_b      = (const float*)d_in[4];
    const float* bias_table = (const float*)d_in[5];
    const int*   rel_idx    = (const int*)d_in[6];
    float* out = (float*)d_out;

    const int nwin = in_sizes[0] / (TOK * CD);   // 8192

    // idempotent, capture-safe (no stream work, no allocation)
    cudaFuncSetAttribute(swin_fused, cudaFuncAttributeMaxDynamicSharedMemorySize, SMEM_BYTES);
    swin_fused<<<nwin, THREADS, SMEM_BYTES>>>(x, qkv_w, qkv_b, out_w, out_b,
                                              bias_table, rel_idx, out);
}

// round 13
// speedup vs baseline: 1.4687x; 1.0142x over previous
#include <cuda_runtime.h>

// SwinWindowAttention fused kernel: one CTA per window, fp32 f32x2 FMA.
// R9 (PASS 2067us): L1=64.4% binding; 7 warps each re-read whole weight tile.
// R10-R12 (unmeasured, timeouts): warp->(row,col) remap: rg=tid&7, cg=tid>>3.
//   Warp spans 4 col-groups x 8 row-groups -> weight read per k-step = 64B
//   contiguous (1 wf, no cross-warp redundancy). s_x padded to 132 f/row,
//   QKV rows padded to 36 f. GEMM smem wf ~ -45%; FMA warp-instrs +14%.
//   bias_table/rel_idx via __ldg (L1-resident, shared across 8192 CTAs).
// R13: resubmission of R12 verbatim (acquisition timeouts; never measured).

#define TOK 49
#define CD  128

namespace {
constexpr int THREADS = 256;
constexpr int XSTR = 132;                  // padded x row stride (floats)
constexpr int RSTR = 36;                   // padded qkv row stride (floats)
constexpr int HSTR = TOK * RSTR;           // per-head stride = 1764
constexpr int TSTR = 4 * HSTR;             // per-tensor stride = 7056
// smem layout (floats):
constexpr int OFF_X    = 0;                // x window [49][132] / attn output  (6468)
constexpr int OFF_QKV  = 6480;             // q,k,v each [4][HSTR]              (21168)
constexpr int OFF_WS   = 27648;            // weight tile transposed [128][132] (16896)
constexpr int SMEM_FLOATS = 44544;
constexpr int SMEM_BYTES  = SMEM_FLOATS * 4;   // 178176 B
constexpr float SCALE = 0.17677669529663687f;  // 32^-0.5
}

// ---- packed f32x2 helpers (sm_103a) ----------------------------------------
__device__ __forceinline__ unsigned long long pk2(float a, float b) {
    unsigned long long r;
    asm("mov.b64 %0, {%1, %2};" : "=l"(r)
        : "r"(__float_as_uint(a)), "r"(__float_as_uint(b)));
    return r;
}
__device__ __forceinline__ void fma2(unsigned long long& d,
                                     unsigned long long a, unsigned long long b) {
    asm("fma.rn.f32x2 %0, %1, %2, %3;" : "=l"(d) : "l"(a), "l"(b), "l"(d));
}
__device__ __forceinline__ void add2(unsigned long long& d, unsigned long long a) {
    asm("add.rn.f32x2 %0, %1, %2;" : "=l"(d) : "l"(a), "l"(d));
}
__device__ __forceinline__ float2 upk(unsigned long long v) {
    unsigned int lo, hi;
    asm("mov.b64 {%0, %1}, %2;" : "=r"(lo), "=r"(hi) : "l"(v));
    return make_float2(__uint_as_float(lo), __uint_as_float(hi));
}

// Stage a [128][128] row-major weight matrix into smem transposed:
// ws[k*132 + c] = w[c*128 + k]. Coalesced LDG.32, conflict-free STS.128.
__device__ __forceinline__ void stage_w(const float* __restrict__ wsrc, float* __restrict__ ws) {
    const int tid = threadIdx.x;
    #pragma unroll
    for (int it = 0; it < 16; ++it) {
        int idx = tid + it * THREADS;   // 0..4095
        int k  = idx & 127;             // lanes consecutive k -> coalesced
        int c0 = (idx >> 7) * 4;
        float a0 = wsrc[(c0 + 0) * 128 + k];
        float a1 = wsrc[(c0 + 1) * 128 + k];
        float a2 = wsrc[(c0 + 2) * 128 + k];
        float a3 = wsrc[(c0 + 3) * 128 + k];
        float4 v; v.x = a0; v.y = a1; v.z = a2; v.w = a3;
        *reinterpret_cast<float4*>(ws + k * 132 + c0) = v;
    }
}

// Same staging by one warp (lane t0 = 0..31), overlapped with attention.
__device__ __forceinline__ void stage_w_warp(const float* __restrict__ wsrc,
                                             float* __restrict__ ws, int t0) {
    #pragma unroll 4
    for (int it = 0; it < 128; ++it) {
        int idx = t0 + it * 32;
        int k  = idx & 127;
        int c0 = (idx >> 7) * 4;
        float a0 = wsrc[(c0 + 0) * 128 + k];
        float a1 = wsrc[(c0 + 1) * 128 + k];
        float a2 = wsrc[(c0 + 2) * 128 + k];
        float a3 = wsrc[(c0 + 3) * 128 + k];
        float4 v; v.x = a0; v.y = a1; v.z = a2; v.w = a3;
        *reinterpret_cast<float4*>(ws + k * 132 + c0) = v;
    }
}

// 7 rows x 4 cols register-tile GEMM over K=128 using f32x2 (col pairs).
__device__ __forceinline__ void gemm_7x4_f32x2(const float* __restrict__ xs,
                                               const float* __restrict__ ws,
                                               int r0, int c0,
                                               unsigned long long acc[7][2]) {
    #pragma unroll 4
    for (int k = 0; k < 128; k += 4) {
        unsigned long long wlo[4], whi[4];
        #pragma unroll
        for (int u = 0; u < 4; ++u) {
            ulonglong2 wv = *reinterpret_cast<const ulonglong2*>(ws + (k + u) * 132 + c0);
            wlo[u] = wv.x; whi[u] = wv.y;       // (c0,c0+1),(c0+2,c0+3)
        }
        #pragma unroll
        for (int r = 0; r < 7; ++r) {
            float4 xv = *reinterpret_cast<const float4*>(xs + (r0 + r) * XSTR + k);
            unsigned long long xx;
            xx = pk2(xv.x, xv.x); fma2(acc[r][0], xx, wlo[0]); fma2(acc[r][1], xx, whi[0]);
            xx = pk2(xv.y, xv.y); fma2(acc[r][0], xx, wlo[1]); fma2(acc[r][1], xx, whi[1]);
            xx = pk2(xv.z, xv.z); fma2(acc[r][0], xx, wlo[2]); fma2(acc[r][1], xx, whi[2]);
            xx = pk2(xv.w, xv.w); fma2(acc[r][0], xx, wlo[3]); fma2(acc[r][1], xx, whi[3]);
        }
    }
}

__global__ void __launch_bounds__(THREADS, 1)
swin_fused(const float* __restrict__ x,
           const float* __restrict__ qkv_w,
           const float* __restrict__ qkv_b,
           const float* __restrict__ out_w,
           const float* __restrict__ out_b,
           const float* __restrict__ bias_table,
           const int*   __restrict__ rel_idx,
           float* __restrict__ out)
{
    extern __shared__ float sm[];
    float* s_x   = sm + OFF_X;
    float* s_qkv = sm + OFF_QKV;
    float* s_ws  = sm + OFF_WS;

    const int tid = threadIdx.x;
    const float* xw = x + (size_t)blockIdx.x * (TOK * CD);

    // ---------------- Phase A: stage x (padded rows) --------------------------------
    for (int i = tid; i < TOK * 32; i += THREADS) {
        int row = i >> 5, c4 = (i & 31) * 4;
        *reinterpret_cast<float4*>(s_x + row * XSTR + c4) =
            *reinterpret_cast<const float4*>(xw + row * CD + c4);
    }

    // GEMM role mapping: warp spans 4 col-groups x 8 row-groups.
    const int rg = tid & 7;             // row-group 0..7 (7 active)
    const int cg = tid >> 3;            // col-group 0..31
    const int r0 = rg * 7;
    const bool gact = (rg < 7);

    // ---------------- Phase B: QKV = x @ qkv_w^T + qkv_b  (3 passes of 128 cols) ----
    for (int p = 0; p < 3; ++p) {
        __syncthreads();                          // x ready / prior-pass readers done
        stage_w(qkv_w + p * 16384, s_ws);
        __syncthreads();
        if (gact) {
            const int c0 = cg * 4;
            unsigned long long acc[7][2];
            float4 bv = *reinterpret_cast<const float4*>(qkv_b + p * 128 + c0);
            #pragma unroll
            for (int r = 0; r < 7; ++r) {
                acc[r][0] = pk2(bv.x, bv.y);
                acc[r][1] = pk2(bv.z, bv.w);
            }
            gemm_7x4_f32x2(s_x, s_ws, r0, c0, acc);
            // scatter: s_qkv[p*TSTR + h*HSTR + row*RSTR + d]
            const int h  = cg >> 3;
            const int d0 = (cg & 7) * 4;
            float* dst = s_qkv + p * TSTR + h * HSTR + d0;
            #pragma unroll
            for (int r = 0; r < 7; ++r) {
                float2 a = upk(acc[r][0]), b = upk(acc[r][1]);
                float4 v; v.x = a.x; v.y = a.y; v.z = b.x; v.w = b.y;
                *reinterpret_cast<float4*>(dst + (r0 + r) * RSTR) = v;
            }
        }
    }
    __syncthreads();

    // ---------------- Phase C: attention (tids<196) || stage out_w (warp 7) ---------
    if (tid < 196) {
        const int h = tid / 49;
        const int i = tid - h * 49;
        const ulonglong2* qrow = reinterpret_cast<const ulonglong2*>(s_qkv + h * HSTR + i * RSTR);
        ulonglong2 qa[8];
        #pragma unroll
        for (int u = 0; u < 8; ++u) qa[u] = qrow[u];

        const float* kbase = s_qkv + TSTR     + h * HSTR;
        const float* vbase = s_qkv + 2 * TSTR + h * HSTR;
        const int*   ri    = rel_idx + i * 49;        // global, L1/L2-resident

        float pr[49];
        float m = -1e30f;
        #pragma unroll
        for (int j = 0; j < 49; ++j) {
            const ulonglong2* kr = reinterpret_cast<const ulonglong2*>(kbase + j * RSTR);
            unsigned long long s0 = 0ull, s1 = 0ull, s2 = 0ull, s3 = 0ull;
            #pragma unroll
            for (int u = 0; u < 4; ++u) {        // 8 ulonglong2 = 32 dims
                ulonglong2 k0 = kr[2 * u], k1 = kr[2 * u + 1];
                fma2(s0, qa[2 * u].x,     k0.x);
                fma2(s1, qa[2 * u].y,     k0.y);
                fma2(s2, qa[2 * u + 1].x, k1.x);
                fma2(s3, qa[2 * u + 1].y, k1.y);
            }
            add2(s0, s1); add2(s2, s3); add2(s0, s2);
            float2 sp = upk(s0);
            float s = sp.x + sp.y;
            float b = __ldg(bias_table + __ldg(ri + j) * 4 + h);
            s = fmaf(s, SCALE, b);
            pr[j] = s;
            m = fmaxf(m, s);
        }
        float sum = 0.f;
        #pragma unroll
        for (int j = 0; j < 49; ++j) {
            float e = __expf(pr[j] - m);
            pr[j] = e;
            sum += e;
        }
        const float inv = 1.f / sum;

        unsigned long long o2[16];
        #pragma unroll
        for (int u = 0; u < 16; ++u) o2[u] = 0ull;
        #pragma unroll
        for (int j = 0; j < 49; ++j) {
            const unsigned long long pp = pk2(pr[j], pr[j]);
            const ulonglong2* vr = reinterpret_cast<const ulonglong2*>(vbase + j * RSTR);
            #pragma unroll
            for (int u = 0; u < 8; ++u) {
                ulonglong2 vv = vr[u];
                fma2(o2[2 * u + 0], pp, vv.x);
                fma2(o2[2 * u + 1], pp, vv.y);
            }
        }
        // write concat-head layout into s_x (padded rows): o_row[i][h*32+d]
        float* od = s_x + i * XSTR + h * 32;
        #pragma unroll
        for (int u = 0; u < 16; ++u) {
            float2 v = upk(o2[u]);
            od[2 * u + 0] = v.x * inv;
            od[2 * u + 1] = v.y * inv;
        }
    } else if (tid >= 224) {
        // Warp 7 (idle in attention) stages out_w concurrently; s_ws unused
        // since the post-Phase-B barrier.
        stage_w_warp(out_w, s_ws, tid - 224);
    }
    __syncthreads();

    // ---------------- Phase D: out = o @ out_w^T + out_b -----------------------------
    if (gact) {
        const int c0 = cg * 4;
        unsigned long long acc[7][2];
        float4 bv = *reinterpret_cast<const float4*>(out_b + c0);
        #pragma unroll
        for (int r = 0; r < 7; ++r) {
            acc[r][0] = pk2(bv.x, bv.y);
            acc[r][1] = pk2(bv.z, bv.w);
        }
        gemm_7x4_f32x2(s_x, s_ws, r0, c0, acc);
        float* dst = out + (size_t)blockIdx.x * (TOK * CD);
        #pragma unroll
        for (int r = 0; r < 7; ++r) {
            float2 a = upk(acc[r][0]), b = upk(acc[r][1]);
            float4 v; v.x = a.x; v.y = a.y; v.z = b.x; v.w = b.y;
            *reinterpret_cast<float4*>(dst + (r0 + r) * CD + c0) = v;
        }
    }
}

extern "C" void kernel_launch(void* const* d_in, const int* in_sizes, int n_in,
                              void* d_out, int out_size) {
    const float* x          = (const float*)d_in[0];
    const float* qkv_w      = (const float*)d_in[1];
    const float* qkv_b      = (const float*)d_in[2];
    const float* out_w      = (const float*)d_in[3];
    const float* out_b      = (const float*)d_in[4];
    const float* bias_table = (const float*)d_in[5];
    const int*   rel_idx    = (const int*)d_in[6];
    float* out = (float*)d_out;

    const int nwin = in_sizes[0] / (TOK * CD);   // 8192

    cudaFuncSetAttribute(swin_fused, cudaFuncAttributeMaxDynamicSharedMemorySize, SMEM_BYTES);
    swin_fused<<<nwin, THREADS, SMEM_BYTES>>>(x, qkv_w, qkv_b, out_w, out_b,
                                              bias_table, rel_idx, out);
}